// round 14
// baseline (speedup 1.0000x reference)
#include <cuda_runtime.h>
#include <cuda_bf16.h>
#include <cstdint>

#define NN  100000
#define EE  1600000
#define PP  800000
#define HEN 20000
#define FIN 128
#define D   64
#define NC  40

// block partitions
#define GHE_BLKS   1250          // HEN*16/256
#define GE2N_BLKS  6250          // NN*16/256
#define S1E_BLKS   98            // (NN+1023)/1024
#define S3E_BLKS   391           // (NN+255)/256
#define GEMM1_BLKS 391           // (NN+255)/256, 8 warps x 32 rows
#define FILLH_BLKS 3125          // PP/256
#define CNTE_BLKS  6250          // EE/256
#define FILLE_HALF 3125          // (EE/2)/256

// ---------------- scratch (device globals; no allocation allowed) ----------------
__device__ float g_xw [NN * D];
__device__ float g_h1 [NN * D];
__device__ float g_h2 [NN * D];
__device__ float g_xg [NN * D];
__device__ float g_t40[NN * NC];
__device__ float g_ef [HEN * D];
__device__ float g_dis  [NN];
__device__ float g_Dninv[NN];
__device__ float g_Binv [HEN];
__device__ float g_Wp[D * NC];      // W_c2 @ W_lp
__device__ float g_bp[NC];          // b_c2 @ W_lp + b_lp
__device__ int g_cntE[NN], g_cntH[HEN], g_cntN[NN];   // static zero-init; re-zeroed after use
__device__ int g_offE[NN + 1], g_offH[HEN + 1], g_offN[NN + 1];
__device__ int g_curE[NN], g_curH[HEN], g_curN[NN];
__device__ int g_csrE[EE];
__device__ int g_csrHn[PP];
__device__ int g_csrNh[PP];
__device__ int g_bsum[512];          // [0:98)=E, [128:226)=N, [256:276)=H

// ---------------- helpers ----------------
__device__ __forceinline__ int sniff64(const void* b) {
    int acc = 0;
    #pragma unroll
    for (int i = 0; i < 8; i++) acc |= ((const int*)b)[2 * i + 1];
    return acc == 0;
}
__device__ __forceinline__ long long ldidx(const void* b, long long i, int m64) {
    return m64 ? ((const long long*)b)[i] : (long long)((const int*)b)[i];
}

// ---------------- hypergraph counting (E counting is deferred into k_build) --------
__global__ void k_cnt_h(const void* hidx) {
    int mh = sniff64(hidx);
    int i = blockIdx.x * blockDim.x + threadIdx.x;
    if (i < PP) {
        int node = (int)ldidx(hidx, i, mh);
        int he   = (int)ldidx(hidx, (long long)PP + i, mh);
        atomicAdd(&g_cntN[node], 1);
        atomicAdd(&g_cntH[he], 1);
    }
}

// ---------------- scan stage 1 for N,H (+ y==2: W_lp fold) -------------------------
__device__ __forceinline__ void scan1_body(const int* cnt, int n, int* excl, int* bs, int bx) {
    __shared__ int wsum[8];
    int t = threadIdx.x;
    int base = bx * 1024 + t * 4;
    int v0 = 0, v1 = 0, v2 = 0, v3 = 0;
    if (base + 0 < n) v0 = cnt[base + 0];
    if (base + 1 < n) v1 = cnt[base + 1];
    if (base + 2 < n) v2 = cnt[base + 2];
    if (base + 3 < n) v3 = cnt[base + 3];
    int tot = v0 + v1 + v2 + v3;
    int lane = t & 31, w = t >> 5;
    int p = tot;
    for (int d = 1; d < 32; d <<= 1) { int u = __shfl_up_sync(~0u, p, d); if (lane >= d) p += u; }
    if (lane == 31) wsum[w] = p;
    __syncthreads();
    int wb = 0;
    for (int i = 0; i < w; i++) wb += wsum[i];
    int e0 = wb + p - tot;
    if (base + 0 < n) excl[base + 0] = e0;
    if (base + 1 < n) excl[base + 1] = e0 + v0;
    if (base + 2 < n) excl[base + 2] = e0 + v0 + v1;
    if (base + 3 < n) excl[base + 3] = e0 + v0 + v1 + v2;
    if (t == 255) bs[bx] = wb + p;
}

__global__ void k_scan1f(const float* __restrict__ W_c2, const float* __restrict__ b_c2,
                         const float* __restrict__ W_lp, const float* __restrict__ b_lp) {
    int t = threadIdx.x;
    if (blockIdx.y == 2) {                      // fold W_lp into W_c2
        if (blockIdx.x != 0) return;
        for (int i = t; i < D * NC + NC; i += 256) {
            if (i < D * NC) {
                int k = i / NC, c = i - k * NC;
                float s = 0.f;
                #pragma unroll
                for (int j = 0; j < NC; j++) s = fmaf(W_c2[k * NC + j], W_lp[j * NC + c], s);
                g_Wp[i] = s;
            } else {
                int c = i - D * NC;
                float s = b_lp[c];
                #pragma unroll
                for (int j = 0; j < NC; j++) s = fmaf(b_c2[j], W_lp[j * NC + c], s);
                g_bp[c] = s;
            }
        }
        return;
    }
    if (blockIdx.y == 0) scan1_body(g_cntN, NN,  g_offN, g_bsum + 128, blockIdx.x);
    else                 scan1_body(g_cntH, HEN, g_offH, g_bsum + 256, blockIdx.x);
}

// ---------------- scan stage 2+3 fused for N,H (block-base via in-block reduce) -----
__global__ void k_scan3_NH() {
    __shared__ int sred[256];
    int t = threadIdx.x;
    int y = blockIdx.y;
    int i = blockIdx.x * 256 + t;
    int c = (blockIdx.x * 256) >> 10;
    const int* bs = g_bsum + (y == 0 ? 128 : 256);
    sred[t] = (t < c) ? bs[t] : 0;
    __syncthreads();
    #pragma unroll
    for (int st = 128; st > 0; st >>= 1) {
        if (t < st) sred[t] += sred[t + st];
        __syncthreads();
    }
    int S = sred[0];
    if (y == 0) {
        if (i < NN) {
            int v = g_offN[i] + S;
            g_offN[i] = v; g_curN[i] = v;
            int dn = g_cntN[i];
            g_Dninv[i] = dn > 0 ? 1.0f / (float)dn : 0.0f;
            g_cntN[i] = 0;
        }
        if (i == 0) g_offN[NN] = PP;
    } else {
        if (i < HEN) {
            int v = g_offH[i] + S;
            g_offH[i] = v; g_curH[i] = v;
            int bh = g_cntH[i];
            g_Binv[i] = bh > 0 ? 1.0f / (float)bh : 0.0f;
            g_cntH[i] = 0;
        }
        if (i == 0) g_offH[HEN] = PP;
    }
}

// ---------------- E-side rider bodies ----------------------------------------------
__device__ __forceinline__ void scan1E_body(int bx) {
    scan1_body(g_cntE, NN, g_offE, g_bsum, bx);
}
__device__ __forceinline__ void scan3E_body(int bx) {
    __shared__ int sred[256];
    int t = threadIdx.x;
    int i = bx * 256 + t;
    int c = (bx * 256) >> 10;
    sred[t] = (t < c) ? g_bsum[t] : 0;
    __syncthreads();
    #pragma unroll
    for (int st = 128; st > 0; st >>= 1) {
        if (t < st) sred[t] += sred[t + st];
        __syncthreads();
    }
    int S = sred[0];
    if (i < NN) {
        int v = g_offE[i] + S;
        g_offE[i] = v; g_curE[i] = v;
        g_dis[i] = rsqrtf((float)g_cntE[i] + 1.0f);
        g_cntE[i] = 0;
    }
    if (i == 0) g_offE[NN] = EE;
}
__device__ __forceinline__ void fillE_body(const void* eidx, long long base, int bx) {
    int me = sniff64(eidx);
    long long i = base + (long long)bx * 256 + threadIdx.x;
    if (i < EE) {
        int src = (int)ldidx(eidx, i, me);
        int dst = (int)ldidx(eidx, (long long)EE + i, me);
        int pos = atomicAdd(&g_curE[dst], 1);
        g_csrE[pos] = src;
    }
}

// ---------------- bf16 split tensor-core GEMM body (C=64) --------------------------
__host__ __device__ constexpr int padw(int v) { int r = v % 32; return v + ((r <= 4) ? (4 - r) : (36 - r)); }

__device__ __forceinline__ void bsplit(float2 q, uint32_t& hi, uint32_t& lo) {
    uint32_t h;
    asm("cvt.rn.bf16x2.f32 %0, %1, %2;" : "=r"(h) : "f"(q.y), "f"(q.x));
    float hx = __uint_as_float(h << 16);
    float hy = __uint_as_float(h & 0xffff0000u);
    float rx = q.x - hx, ry = q.y - hy;
    uint32_t l;
    asm("cvt.rn.bf16x2.f32 %0, %1, %2;" : "=r"(l) : "f"(ry), "f"(rx));
    hi = h; lo = l;
}
#define MMA16816(c, a, b0, b1)                                                     \
    asm volatile("mma.sync.aligned.m16n8k16.row.col.f32.bf16.bf16.f32 "            \
                 "{%0,%1,%2,%3}, {%4,%5,%6,%7}, {%8,%9}, {%0,%1,%2,%3};"           \
                 : "+f"(c[0]), "+f"(c[1]), "+f"(c[2]), "+f"(c[3])                  \
                 : "r"(a[0]), "r"(a[1]), "r"(a[2]), "r"(a[3]), "r"(b0), "r"(b1))

template<int K1, int K2, int WARPS>
__device__ __forceinline__ void gemm_body(
    const float* __restrict__ A1, const float* __restrict__ A2,
    const float* __restrict__ W, float* __restrict__ out,
    const float* __restrict__ rowscale, int bx)
{
    constexpr int KT = K1 + K2;
    constexpr int C = 64;
    constexpr int KPW = padw(KT / 2);
    constexpr int KPE = KPW * 2;
    extern __shared__ unsigned char smraw[];
    __nv_bfloat16* WtHi = (__nv_bfloat16*)smraw;
    __nv_bfloat16* WtLo = WtHi + C * KPE;

    int tid = threadIdx.x;
    for (int idx = tid; idx < KT * C; idx += WARPS * 32) {
        int k = idx >> 6, n = idx & 63;
        float w = W[idx];
        __nv_bfloat16 h = __float2bfloat16(w);
        float lo = w - __bfloat162float(h);
        WtHi[n * KPE + k] = h;
        WtLo[n * KPE + k] = __float2bfloat16(lo);
    }
    __syncthreads();

    const uint32_t* WH = (const uint32_t*)WtHi;
    const uint32_t* WL = (const uint32_t*)WtLo;

    int w = tid >> 5, lane = tid & 31;
    int g = lane >> 2, t = lane & 3;
    int m0 = bx * (WARPS * 32) + w * 32;
    int rows[4] = { m0 + g, m0 + g + 8, m0 + 16 + g, m0 + 24 + g };
    int rc[4];
    #pragma unroll
    for (int i = 0; i < 4; i++) rc[i] = rows[i] < NN ? rows[i] : NN - 1;

    float acc[2][8][4] = {};

    for (int kc = 0; kc < KT / 16; kc++) {
        int kk = kc * 16;
        uint32_t ah[2][4], al[2][4];
        #pragma unroll
        for (int f = 0; f < 2; f++) {
            const float *p0, *p1;
            if (K2 == 0 || kk < K1) {
                p0 = A1 + (size_t)rc[2 * f] * K1 + kk;
                p1 = A1 + (size_t)rc[2 * f + 1] * K1 + kk;
            } else {
                p0 = A2 + (size_t)rc[2 * f] * K2 + (kk - K1);
                p1 = A2 + (size_t)rc[2 * f + 1] * K2 + (kk - K1);
            }
            float2 q0 = *(const float2*)(p0 + 2 * t);
            float2 q1 = *(const float2*)(p1 + 2 * t);
            float2 q2 = *(const float2*)(p0 + 2 * t + 8);
            float2 q3 = *(const float2*)(p1 + 2 * t + 8);
            bsplit(q0, ah[f][0], al[f][0]);
            bsplit(q1, ah[f][1], al[f][1]);
            bsplit(q2, ah[f][2], al[f][2]);
            bsplit(q3, ah[f][3], al[f][3]);
        }
        #pragma unroll
        for (int s = 0; s < 8; s++) {
            int wi = (s * 8 + g) * KPW + kc * 8 + t;
            uint32_t bh0 = WH[wi], bh1 = WH[wi + 4];
            uint32_t bl0 = WL[wi], bl1 = WL[wi + 4];
            #pragma unroll
            for (int f = 0; f < 2; f++) {
                MMA16816(acc[f][s], ah[f], bh0, bh1);
                MMA16816(acc[f][s], al[f], bh0, bh1);
                MMA16816(acc[f][s], ah[f], bl0, bl1);
            }
        }
    }

    float rs[4] = {1.f, 1.f, 1.f, 1.f};
    if (rowscale) {
        #pragma unroll
        for (int i = 0; i < 4; i++) rs[i] = rowscale[rc[i]];
    }
    #pragma unroll
    for (int f = 0; f < 2; f++) {
        #pragma unroll
        for (int s = 0; s < 8; s++) {
            int col = s * 8 + 2 * t;
            int ra = rows[2 * f], rb = rows[2 * f + 1];
            if (ra < NN) {
                float2 v = { acc[f][s][0] * rs[2 * f], acc[f][s][1] * rs[2 * f] };
                *(float2*)(out + (size_t)ra * 64 + col) = v;
            }
            if (rb < NN) {
                float2 v = { acc[f][s][2] * rs[2 * f + 1], acc[f][s][3] * rs[2 * f + 1] };
                *(float2*)(out + (size_t)rb * 64 + col) = v;
            }
        }
    }
}

template<int K1, int K2>
__global__ void k_mma(const float* __restrict__ A1, const float* __restrict__ A2,
                      const float* __restrict__ W, float* __restrict__ out,
                      const float* __restrict__ rowscale) {
    gemm_body<K1, K2, 4>(A1, A2, W, out, rowscale, blockIdx.x);
}

// ---------------- k_build: GEMM1 + fillH + cntE in one launch ----------------------
__global__ void k_build(const void* eidx, const void* hidx,
                        const float* __restrict__ x, const float* __restrict__ W,
                        float* __restrict__ xw) {
    int bid = blockIdx.x;
    if (bid < GEMM1_BLKS) {
        gemm_body<FIN, 0, 8>(x, nullptr, W, xw, nullptr, bid);
        return;
    }
    bid -= GEMM1_BLKS;
    if (bid < FILLH_BLKS) {                       // fill hypergraph CSRs
        int mh = sniff64(hidx);
        int i = bid * 256 + threadIdx.x;
        if (i < PP) {
            int node = (int)ldidx(hidx, i, mh);
            int he   = (int)ldidx(hidx, (long long)PP + i, mh);
            int p1 = atomicAdd(&g_curH[he], 1);   g_csrHn[p1] = node;
            int p2 = atomicAdd(&g_curN[node], 1); g_csrNh[p2] = he;
        }
        return;
    }
    bid -= FILLH_BLKS;                            // count E in-degrees
    int me = sniff64(eidx);
    int i = bid * 256 + threadIdx.x;
    if (i < EE) {
        int dst = (int)ldidx(eidx, (long long)EE + i, me);
        atomicAdd(&g_cntE[dst], 1);
    }
}

// ---------------- FFMA GEMM (C=40): out = rowscale*(A@W) ---------------------------
template<int K1, int C>
__global__ void k_gemm(const float* __restrict__ A1, const float* __restrict__ W,
                       float* __restrict__ out, const float* __restrict__ rowscale) {
    constexpr int CG = C / 4;
    __shared__ float Ws[K1 * C];
    int tid = threadIdx.x;
    for (int i = tid; i < K1 * C; i += CG * 16) Ws[i] = W[i];
    __syncthreads();
    int cg = tid % CG, rg = tid / CG;
    int row0 = blockIdx.x * 64 + rg * 4;
    int r[4];
    #pragma unroll
    for (int j = 0; j < 4; j++) { int rr = row0 + j; r[j] = rr < NN ? rr : NN - 1; }

    float acc[4][4] = {};
    #pragma unroll 2
    for (int k = 0; k < K1; k += 4) {
        float a[4][4];
        #pragma unroll
        for (int j = 0; j < 4; j++)
            *(float4*)a[j] = *(const float4*)(A1 + (size_t)r[j] * K1 + k);
        #pragma unroll
        for (int kk = 0; kk < 4; kk++) {
            float w[4];
            *(float4*)w = *(const float4*)&Ws[(k + kk) * C + cg * 4];
            #pragma unroll
            for (int j = 0; j < 4; j++)
                #pragma unroll
                for (int c = 0; c < 4; c++)
                    acc[j][c] = fmaf(a[j][kk], w[c], acc[j][c]);
        }
    }
    #pragma unroll
    for (int j = 0; j < 4; j++) {
        int rr = row0 + j;
        if (rr >= NN) break;
        float s = rowscale ? rowscale[rr] : 1.0f;
        float4 o;
        o.x = acc[j][0] * s; o.y = acc[j][1] * s; o.z = acc[j][2] * s; o.w = acc[j][3] * s;
        *(float4*)(out + (size_t)rr * C + cg * 4) = o;
    }
}

// ---------------- gathers (CSR, 8-unroll dual accumulators) ------------------------
#define ACC4(acc, v) { acc.x += v.x; acc.y += v.y; acc.z += v.z; acc.w += v.w; }
#define GLOOP8(CSR, SRC, PITCH)                                                    \
    float4 acc = make_float4(0.f, 0.f, 0.f, 0.f);                                  \
    float4 ac2 = make_float4(0.f, 0.f, 0.f, 0.f);                                  \
    int i = s;                                                                     \
    for (; i + 7 < e; i += 8) {                                                    \
        int n0 = CSR[i],     n1 = CSR[i + 1], n2 = CSR[i + 2], n3 = CSR[i + 3];    \
        int n4 = CSR[i + 4], n5 = CSR[i + 5], n6 = CSR[i + 6], n7 = CSR[i + 7];    \
        float4 v0 = *(const float4*)(SRC + (size_t)n0 * PITCH + l * 4);            \
        float4 v1 = *(const float4*)(SRC + (size_t)n1 * PITCH + l * 4);            \
        float4 v2 = *(const float4*)(SRC + (size_t)n2 * PITCH + l * 4);            \
        float4 v3 = *(const float4*)(SRC + (size_t)n3 * PITCH + l * 4);            \
        float4 v4 = *(const float4*)(SRC + (size_t)n4 * PITCH + l * 4);            \
        float4 v5 = *(const float4*)(SRC + (size_t)n5 * PITCH + l * 4);            \
        float4 v6 = *(const float4*)(SRC + (size_t)n6 * PITCH + l * 4);            \
        float4 v7 = *(const float4*)(SRC + (size_t)n7 * PITCH + l * 4);            \
        ACC4(acc, v0); ACC4(ac2, v1); ACC4(acc, v2); ACC4(ac2, v3);                \
        ACC4(acc, v4); ACC4(ac2, v5); ACC4(acc, v6); ACC4(ac2, v7);                \
    }                                                                              \
    for (; i + 3 < e; i += 4) {                                                    \
        int n0 = CSR[i], n1 = CSR[i + 1], n2 = CSR[i + 2], n3 = CSR[i + 3];        \
        float4 v0 = *(const float4*)(SRC + (size_t)n0 * PITCH + l * 4);            \
        float4 v1 = *(const float4*)(SRC + (size_t)n1 * PITCH + l * 4);            \
        float4 v2 = *(const float4*)(SRC + (size_t)n2 * PITCH + l * 4);            \
        float4 v3 = *(const float4*)(SRC + (size_t)n3 * PITCH + l * 4);            \
        ACC4(acc, v0); ACC4(ac2, v1); ACC4(acc, v2); ACC4(ac2, v3);                \
    }                                                                              \
    for (; i < e; i++) {                                                           \
        int n0 = CSR[i];                                                           \
        float4 v0 = *(const float4*)(SRC + (size_t)n0 * PITCH + l * 4);            \
        ACC4(acc, v0);                                                             \
    }                                                                              \
    acc.x += ac2.x; acc.y += ac2.y; acc.z += ac2.z; acc.w += ac2.w;

__device__ __forceinline__ void gath_he_body(const float* __restrict__ xw, int bid) {
    int t = bid * 256 + threadIdx.x;
    int he = t >> 4, l = t & 15;
    if (he >= HEN) return;
    int s = g_offH[he], e = g_offH[he + 1];
    GLOOP8(g_csrHn, xw, D)
    float b = g_Binv[he];
    acc.x *= b; acc.y *= b; acc.z *= b; acc.w *= b;
    *(float4*)(g_ef + (size_t)he * D + l * 4) = acc;
}

__device__ __forceinline__ void gath_e2n_body(const float* __restrict__ bias,
                                              float* __restrict__ out, int relu, int bid) {
    int t = bid * 256 + threadIdx.x;
    int node = t >> 4, l = t & 15;
    if (node >= NN) return;
    int s = g_offN[node], e = g_offN[node + 1];
    GLOOP8(g_csrNh, g_ef, D)
    float dv = g_Dninv[node];
    float4 bb = *(const float4*)(bias + l * 4);
    float4 o;
    o.x = dv * acc.x + bb.x; o.y = dv * acc.y + bb.y;
    o.z = dv * acc.z + bb.z; o.w = dv * acc.w + bb.w;
    if (relu) {
        o.x = fmaxf(o.x, 0.f); o.y = fmaxf(o.y, 0.f);
        o.z = fmaxf(o.z, 0.f); o.w = fmaxf(o.w, 0.f);
    }
    *(float4*)(out + (size_t)node * D + l * 4) = o;
}

// gather kernels with E-side riders
__global__ void k_gath_he1(const float* __restrict__ xw) {
    if (blockIdx.x < GHE_BLKS) gath_he_body(xw, blockIdx.x);
    else                       scan1E_body(blockIdx.x - GHE_BLKS);
}
__global__ void k_gath_e2n1(const float* __restrict__ bias, float* __restrict__ out) {
    if (blockIdx.x < GE2N_BLKS) gath_e2n_body(bias, out, 1, blockIdx.x);
    else                        scan3E_body(blockIdx.x - GE2N_BLKS);
}
__global__ void k_gath_he2(const float* __restrict__ xw, const void* eidx) {
    if (blockIdx.x < GHE_BLKS) gath_he_body(xw, blockIdx.x);
    else                       fillE_body(eidx, 0, blockIdx.x - GHE_BLKS);
}
__global__ void k_gath_e2n2(const float* __restrict__ bias, float* __restrict__ out,
                            const void* eidx) {
    if (blockIdx.x < GE2N_BLKS) gath_e2n_body(bias, out, 0, blockIdx.x);
    else                        fillE_body(eidx, EE / 2, blockIdx.x - GE2N_BLKS);
}

__global__ void k_gcn64(const float* __restrict__ xwd, const float* __restrict__ bias,
                        float* __restrict__ out) {
    int t = blockIdx.x * blockDim.x + threadIdx.x;
    int node = t >> 4, l = t & 15;
    if (node >= NN) return;
    int s = g_offE[node], e = g_offE[node + 1];
    GLOOP8(g_csrE, xwd, D)
    float4 self = *(const float4*)(xwd + (size_t)node * D + l * 4);
    float ds = g_dis[node];
    float4 bb = *(const float4*)(bias + l * 4);
    float4 o;
    o.x = fmaxf(ds * (acc.x + self.x) + bb.x, 0.f);
    o.y = fmaxf(ds * (acc.y + self.y) + bb.y, 0.f);
    o.z = fmaxf(ds * (acc.z + self.z) + bb.z, 0.f);
    o.w = fmaxf(ds * (acc.w + self.w) + bb.w, 0.f);
    *(float4*)(out + (size_t)node * D + l * 4) = o;
}

// gcn2 gather + folded head: writes FINAL output with bias g_bp
__global__ void k_gcn40(float* __restrict__ out) {
    int t = blockIdx.x * blockDim.x + threadIdx.x;
    int node = t / 10, l = t % 10;
    if (node >= NN) return;
    int s = g_offE[node], e = g_offE[node + 1];
    GLOOP8(g_csrE, g_t40, NC)
    float4 self = *(const float4*)(g_t40 + (size_t)node * NC + l * 4);
    float ds = g_dis[node];
    float4 bb = *(const float4*)(g_bp + l * 4);
    float4 o;
    o.x = ds * (acc.x + self.x) + bb.x;
    o.y = ds * (acc.y + self.y) + bb.y;
    o.z = ds * (acc.z + self.z) + bb.z;
    o.w = ds * (acc.w + self.w) + bb.w;
    *(float4*)(out + (size_t)node * NC + l * 4) = o;
}

// ---------------- launch (single stream) ----------------
extern "C" void kernel_launch(void* const* d_in, const int* in_sizes, int n_in,
                              void* d_out, int out_size) {
    const float* x    = (const float*)d_in[0];
    const void*  eidx = d_in[1];
    const void*  hidx = d_in[2];
    const float* W_h1 = (const float*)d_in[3];
    const float* b_h1 = (const float*)d_in[4];
    const float* W_h2 = (const float*)d_in[5];
    const float* b_h2 = (const float*)d_in[6];
    const float* W_c1 = (const float*)d_in[7];
    const float* b_c1 = (const float*)d_in[8];
    const float* W_c2 = (const float*)d_in[9];
    const float* b_c2 = (const float*)d_in[10];
    const float* W_lp = (const float*)d_in[11];
    const float* b_lp = (const float*)d_in[12];
    float* out = (float*)d_out;

    float *p_xw, *p_h1, *p_h2, *p_xg, *p_t40, *p_dis, *p_Wp;
    cudaGetSymbolAddress((void**)&p_xw,  g_xw);
    cudaGetSymbolAddress((void**)&p_h1,  g_h1);
    cudaGetSymbolAddress((void**)&p_h2,  g_h2);
    cudaGetSymbolAddress((void**)&p_xg,  g_xg);
    cudaGetSymbolAddress((void**)&p_t40, g_t40);
    cudaGetSymbolAddress((void**)&p_dis, g_dis);
    cudaGetSymbolAddress((void**)&p_Wp,  g_Wp);

    const int B = 256;
    const int GR  = (NN + 63) / 64;
    const int GRM = (NN + 127) / 128;

    const int SH128 = 2 * 64 * padw(128 / 2) * 4;   // 34816
    const int SH64  = 2 * 64 * padw(64 / 2) * 4;    // 18432
    const int SH192 = 2 * 64 * padw(192 / 2) * 4;   // 51200 (>48KB)
    cudaFuncSetAttribute(k_mma<D, 0>,   cudaFuncAttributeMaxDynamicSharedMemorySize, SH64);
    cudaFuncSetAttribute(k_mma<FIN, D>, cudaFuncAttributeMaxDynamicSharedMemorySize, SH192);
    cudaFuncSetAttribute(k_build,       cudaFuncAttributeMaxDynamicSharedMemorySize, SH128);

    // ---- hypergraph CSR + deferred E-CSR (riders) ----
    k_cnt_h<<<FILLH_BLKS, B>>>(hidx);
    k_scan1f<<<dim3(S1E_BLKS, 3), B>>>(W_c2, b_c2, W_lp, b_lp);
    k_scan3_NH<<<dim3(S3E_BLKS, 2), B>>>();
    k_build<<<GEMM1_BLKS + FILLH_BLKS + CNTE_BLKS, B, SH128>>>(eidx, hidx, x, W_h1, p_xw);

    // ---- hyperconv 1 (E-scan riders) ----
    k_gath_he1<<<GHE_BLKS + S1E_BLKS, B>>>(p_xw);
    k_gath_e2n1<<<GE2N_BLKS + S3E_BLKS, B>>>(b_h1, p_h1);

    // ---- hyperconv 2 (E-fill riders) ----
    k_mma<D, 0><<<GRM, 128, SH64>>>(p_h1, nullptr, W_h2, p_xw, nullptr);
    k_gath_he2<<<GHE_BLKS + FILLE_HALF, B>>>(p_xw, eidx);
    k_gath_e2n2<<<GE2N_BLKS + FILLE_HALF, B>>>(b_h2, p_h2, eidx);

    // ---- gcn 1 (concat input, dis-prescaled) ----
    k_mma<FIN, D><<<GRM, 128, SH192>>>(x, p_h2, W_c1, p_xw, p_dis);
    k_gcn64<<<(NN * 16 + B - 1) / B, B>>>(p_xw, b_c1, p_xg);

    // ---- gcn 2 with folded linear head (writes final out) ----
    k_gemm<D, NC><<<GR, 160>>>(p_xg, p_Wp, p_t40, p_dis);
    k_gcn40<<<(NN * 10 + 319) / 320, 320>>>(out);
}

// round 16
// speedup vs baseline: 1.0178x; 1.0178x over previous
#include <cuda_runtime.h>
#include <cuda_bf16.h>
#include <cuda_fp16.h>
#include <cstdint>

#define NN  100000
#define EE  1600000
#define PP  800000
#define HEN 20000
#define FIN 128
#define D   64
#define NC  40

// ---------------- scratch (device globals; no allocation allowed) ----------------
__device__ float  g_xw [NN * D];
__device__ float  g_h1 [NN * D];
__device__ float  g_h2 [NN * D];
__device__ float  g_xg [NN * D];
__device__ __half g_xwh[NN * D];     // gcn1 xwd in fp16 (gather source)
__device__ __half g_t40h[NN * NC];   // gcn2 xwd in fp16 (gather source)
__device__ float  g_ef [HEN * D];
__device__ float  g_dis  [NN];
__device__ float  g_Dninv[NN];
__device__ float  g_Binv [HEN];
__device__ float  g_Wp[D * NC];      // W_c2 @ W_lp
__device__ float  g_bp[NC];          // b_c2 @ W_lp + b_lp
__device__ int g_cntE[NN], g_cntH[HEN], g_cntN[NN];   // static zero-init; re-zeroed in fill
__device__ int g_offE[NN + 1], g_offH[HEN + 1], g_offN[NN + 1];
__device__ int g_curE[NN], g_curH[HEN], g_curN[NN];
__device__ int g_csrE[EE];
__device__ int g_csrHn[PP];
__device__ int g_csrNh[PP];
__device__ int g_bsum[512];

// ---------------- helpers ----------------
__device__ __forceinline__ int sniff64(const void* b) {
    int acc = 0;
    #pragma unroll
    for (int i = 0; i < 8; i++) acc |= ((const int*)b)[2 * i + 1];
    return acc == 0;
}
__device__ __forceinline__ long long ldidx(const void* b, long long i, int m64) {
    return m64 ? ((const long long*)b)[i] : (long long)((const int*)b)[i];
}

// ---------------- fused counting ----------------
__global__ void k_cnt(const void* eidx, const void* hidx) {
    int me = sniff64(eidx), mh = sniff64(hidx);
    int i = blockIdx.x * blockDim.x + threadIdx.x;
    if (i < EE) {
        int dst = (int)ldidx(eidx, (long long)EE + i, me);
        atomicAdd(&g_cntE[dst], 1);
    }
    if (i < PP) {
        int node = (int)ldidx(hidx, i, mh);
        int he   = (int)ldidx(hidx, (long long)PP + i, mh);
        atomicAdd(&g_cntN[node], 1);
        atomicAdd(&g_cntH[he], 1);
    }
}

// ---------------- scan stage 1 (y: 0=E,1=N,2=H; y==3: W_lp fold) --------------------
__global__ void k_scan1f(const float* __restrict__ W_c2, const float* __restrict__ b_c2,
                         const float* __restrict__ W_lp, const float* __restrict__ b_lp) {
    int t = threadIdx.x;
    if (blockIdx.y == 3) {
        if (blockIdx.x != 0) return;
        for (int i = t; i < D * NC + NC; i += 256) {
            if (i < D * NC) {
                int k = i / NC, c = i - k * NC;
                float s = 0.f;
                #pragma unroll
                for (int j = 0; j < NC; j++) s = fmaf(W_c2[k * NC + j], W_lp[j * NC + c], s);
                g_Wp[i] = s;
            } else {
                int c = i - D * NC;
                float s = b_lp[c];
                #pragma unroll
                for (int j = 0; j < NC; j++) s = fmaf(b_c2[j], W_lp[j * NC + c], s);
                g_bp[c] = s;
            }
        }
        return;
    }
    const int* cnt; int n; int* excl; int* bs;
    if (blockIdx.y == 0)      { cnt = g_cntE; n = NN;  excl = g_offE; bs = g_bsum;       }
    else if (blockIdx.y == 1) { cnt = g_cntN; n = NN;  excl = g_offN; bs = g_bsum + 128; }
    else                      { cnt = g_cntH; n = HEN; excl = g_offH; bs = g_bsum + 256; }
    __shared__ int wsum[8];
    int base = blockIdx.x * 1024 + t * 4;
    int v0 = 0, v1 = 0, v2 = 0, v3 = 0;
    if (base + 0 < n) v0 = cnt[base + 0];
    if (base + 1 < n) v1 = cnt[base + 1];
    if (base + 2 < n) v2 = cnt[base + 2];
    if (base + 3 < n) v3 = cnt[base + 3];
    int tot = v0 + v1 + v2 + v3;
    int lane = t & 31, w = t >> 5;
    int p = tot;
    for (int d = 1; d < 32; d <<= 1) { int u = __shfl_up_sync(~0u, p, d); if (lane >= d) p += u; }
    if (lane == 31) wsum[w] = p;
    __syncthreads();
    int wb = 0;
    for (int i = 0; i < w; i++) wb += wsum[i];
    int e0 = wb + p - tot;
    if (base + 0 < n) excl[base + 0] = e0;
    if (base + 1 < n) excl[base + 1] = e0 + v0;
    if (base + 2 < n) excl[base + 2] = e0 + v0 + v1;
    if (base + 3 < n) excl[base + 3] = e0 + v0 + v1 + v2;
    if (t == 255) bs[blockIdx.x] = wb + p;
}

// ---------------- scan stage 2+3 fused (block-base via in-block reduce) -------------
__global__ void k_scan3f() {
    __shared__ int sred[256];
    int t = threadIdx.x;
    int y = blockIdx.y;
    int i = blockIdx.x * 256 + t;
    int c = (blockIdx.x * 256) >> 10;
    const int* bs = g_bsum + (y == 0 ? 0 : (y == 1 ? 128 : 256));
    sred[t] = (t < c) ? bs[t] : 0;
    __syncthreads();
    #pragma unroll
    for (int st = 128; st > 0; st >>= 1) {
        if (t < st) sred[t] += sred[t + st];
        __syncthreads();
    }
    int S = sred[0];
    if (y == 0) {
        if (i < NN) {
            int v = g_offE[i] + S;
            g_offE[i] = v; g_curE[i] = v;
            g_dis[i] = rsqrtf((float)g_cntE[i] + 1.0f);
            int dn = g_cntN[i];
            g_Dninv[i] = dn > 0 ? 1.0f / (float)dn : 0.0f;
        }
        if (i < HEN) {
            int bh = g_cntH[i];
            g_Binv[i] = bh > 0 ? 1.0f / (float)bh : 0.0f;
        }
        if (i == 0) g_offE[NN] = EE;
    } else if (y == 1) {
        if (i < NN) {
            int v = g_offN[i] + S;
            g_offN[i] = v; g_curN[i] = v;
        }
        if (i == 0) g_offN[NN] = PP;
    } else {
        if (i < HEN) {
            int v = g_offH[i] + S;
            g_offH[i] = v; g_curH[i] = v;
        }
        if (i == 0) g_offH[HEN] = PP;
    }
}

// ---------------- bf16 split tensor-core GEMM body (C=64) --------------------------
__host__ __device__ constexpr int padw(int v) { int r = v % 32; return v + ((r <= 4) ? (4 - r) : (36 - r)); }

__device__ __forceinline__ void bsplit(float2 q, uint32_t& hi, uint32_t& lo) {
    uint32_t h;
    asm("cvt.rn.bf16x2.f32 %0, %1, %2;" : "=r"(h) : "f"(q.y), "f"(q.x));
    float hx = __uint_as_float(h << 16);
    float hy = __uint_as_float(h & 0xffff0000u);
    float rx = q.x - hx, ry = q.y - hy;
    uint32_t l;
    asm("cvt.rn.bf16x2.f32 %0, %1, %2;" : "=r"(l) : "f"(ry), "f"(rx));
    hi = h; lo = l;
}
#define MMA16816(c, a, b0, b1)                                                     \
    asm volatile("mma.sync.aligned.m16n8k16.row.col.f32.bf16.bf16.f32 "            \
                 "{%0,%1,%2,%3}, {%4,%5,%6,%7}, {%8,%9}, {%0,%1,%2,%3};"           \
                 : "+f"(c[0]), "+f"(c[1]), "+f"(c[2]), "+f"(c[3])                  \
                 : "r"(a[0]), "r"(a[1]), "r"(a[2]), "r"(a[3]), "r"(b0), "r"(b1))

// HOUT: 0 -> fp32 out, 1 -> fp16 out (outh)
template<int K1, int K2, int WARPS, int HOUT>
__device__ __forceinline__ void gemm_body(
    const float* __restrict__ A1, const float* __restrict__ A2,
    const float* __restrict__ W, float* __restrict__ out, __half* __restrict__ outh,
    const float* __restrict__ rowscale, int bx)
{
    constexpr int KT = K1 + K2;
    constexpr int C = 64;
    constexpr int KPW = padw(KT / 2);
    constexpr int KPE = KPW * 2;
    extern __shared__ unsigned char smraw[];
    __nv_bfloat16* WtHi = (__nv_bfloat16*)smraw;
    __nv_bfloat16* WtLo = WtHi + C * KPE;

    int tid = threadIdx.x;
    for (int idx = tid; idx < KT * C; idx += WARPS * 32) {
        int k = idx >> 6, n = idx & 63;
        float w = W[idx];
        __nv_bfloat16 h = __float2bfloat16(w);
        float lo = w - __bfloat162float(h);
        WtHi[n * KPE + k] = h;
        WtLo[n * KPE + k] = __float2bfloat16(lo);
    }
    __syncthreads();

    const uint32_t* WH = (const uint32_t*)WtHi;
    const uint32_t* WL = (const uint32_t*)WtLo;

    int w = tid >> 5, lane = tid & 31;
    int g = lane >> 2, t = lane & 3;
    int m0 = bx * (WARPS * 32) + w * 32;
    int rows[4] = { m0 + g, m0 + g + 8, m0 + 16 + g, m0 + 24 + g };
    int rc[4];
    #pragma unroll
    for (int i = 0; i < 4; i++) rc[i] = rows[i] < NN ? rows[i] : NN - 1;

    float acc[2][8][4] = {};

    for (int kc = 0; kc < KT / 16; kc++) {
        int kk = kc * 16;
        uint32_t ah[2][4], al[2][4];
        #pragma unroll
        for (int f = 0; f < 2; f++) {
            const float *p0, *p1;
            if (K2 == 0 || kk < K1) {
                p0 = A1 + (size_t)rc[2 * f] * K1 + kk;
                p1 = A1 + (size_t)rc[2 * f + 1] * K1 + kk;
            } else {
                p0 = A2 + (size_t)rc[2 * f] * K2 + (kk - K1);
                p1 = A2 + (size_t)rc[2 * f + 1] * K2 + (kk - K1);
            }
            float2 q0 = *(const float2*)(p0 + 2 * t);
            float2 q1 = *(const float2*)(p1 + 2 * t);
            float2 q2 = *(const float2*)(p0 + 2 * t + 8);
            float2 q3 = *(const float2*)(p1 + 2 * t + 8);
            bsplit(q0, ah[f][0], al[f][0]);
            bsplit(q1, ah[f][1], al[f][1]);
            bsplit(q2, ah[f][2], al[f][2]);
            bsplit(q3, ah[f][3], al[f][3]);
        }
        #pragma unroll
        for (int s = 0; s < 8; s++) {
            int wi = (s * 8 + g) * KPW + kc * 8 + t;
            uint32_t bh0 = WH[wi], bh1 = WH[wi + 4];
            uint32_t bl0 = WL[wi], bl1 = WL[wi + 4];
            #pragma unroll
            for (int f = 0; f < 2; f++) {
                MMA16816(acc[f][s], ah[f], bh0, bh1);
                MMA16816(acc[f][s], al[f], bh0, bh1);
                MMA16816(acc[f][s], ah[f], bl0, bl1);
            }
        }
    }

    float rs[4] = {1.f, 1.f, 1.f, 1.f};
    if (rowscale) {
        #pragma unroll
        for (int i = 0; i < 4; i++) rs[i] = rowscale[rc[i]];
    }
    #pragma unroll
    for (int f = 0; f < 2; f++) {
        #pragma unroll
        for (int s = 0; s < 8; s++) {
            int col = s * 8 + 2 * t;
            int ra = rows[2 * f], rb = rows[2 * f + 1];
            if (ra < NN) {
                float vx = acc[f][s][0] * rs[2 * f], vy = acc[f][s][1] * rs[2 * f];
                if (HOUT) *(__half2*)(outh + (size_t)ra * 64 + col) = __floats2half2_rn(vx, vy);
                else      *(float2*)(out  + (size_t)ra * 64 + col) = make_float2(vx, vy);
            }
            if (rb < NN) {
                float vx = acc[f][s][2] * rs[2 * f + 1], vy = acc[f][s][3] * rs[2 * f + 1];
                if (HOUT) *(__half2*)(outh + (size_t)rb * 64 + col) = __floats2half2_rn(vx, vy);
                else      *(float2*)(out  + (size_t)rb * 64 + col) = make_float2(vx, vy);
            }
        }
    }
}

template<int K1, int K2>
__global__ void k_mma(const float* __restrict__ A1, const float* __restrict__ A2,
                      const float* __restrict__ W, float* __restrict__ out,
                      const float* __restrict__ rowscale) {
    gemm_body<K1, K2, 4, 0>(A1, A2, W, out, nullptr, rowscale, blockIdx.x);
}
template<int K1, int K2>
__global__ void k_mma_h(const float* __restrict__ A1, const float* __restrict__ A2,
                        const float* __restrict__ W, __half* __restrict__ outh,
                        const float* __restrict__ rowscale) {
    gemm_body<K1, K2, 4, 1>(A1, A2, W, nullptr, outh, rowscale, blockIdx.x);
}

// ---------------- fused: CSR fill + GEMM1 (x@W_h1) in one launch -------------------
#define GEMM_BLKS ((NN + 255) / 256)
__global__ void k_fill_gemm(const void* eidx, const void* hidx,
                            const float* __restrict__ x, const float* __restrict__ W,
                            float* __restrict__ xw) {
    if (blockIdx.x < GEMM_BLKS) {
        gemm_body<FIN, 0, 8, 0>(x, nullptr, W, xw, nullptr, nullptr, blockIdx.x);
        return;
    }
    int bid = blockIdx.x - GEMM_BLKS;
    int me = sniff64(eidx), mh = sniff64(hidx);
    int i = bid * blockDim.x + threadIdx.x;
    if (i < EE) {
        int src = (int)ldidx(eidx, i, me);
        int dst = (int)ldidx(eidx, (long long)EE + i, me);
        int pos = atomicAdd(&g_curE[dst], 1);
        g_csrE[pos] = src;
    }
    if (i < PP) {
        int node = (int)ldidx(hidx, i, mh);
        int he   = (int)ldidx(hidx, (long long)PP + i, mh);
        int p1 = atomicAdd(&g_curH[he], 1);   g_csrHn[p1] = node;
        int p2 = atomicAdd(&g_curN[node], 1); g_csrNh[p2] = he;
    }
    if (i < NN) { g_cntE[i] = 0; g_cntN[i] = 0; }
    if (i < HEN) g_cntH[i] = 0;
}

// ---------------- FFMA GEMM (C=40, fp16 out): t40h = rowscale*(A@W) ----------------
template<int K1, int C>
__global__ void k_gemm_h(const float* __restrict__ A1, const float* __restrict__ W,
                         __half* __restrict__ outh, const float* __restrict__ rowscale) {
    constexpr int CG = C / 4;
    __shared__ float Ws[K1 * C];
    int tid = threadIdx.x;
    for (int i = tid; i < K1 * C; i += CG * 16) Ws[i] = W[i];
    __syncthreads();
    int cg = tid % CG, rg = tid / CG;
    int row0 = blockIdx.x * 64 + rg * 4;
    int r[4];
    #pragma unroll
    for (int j = 0; j < 4; j++) { int rr = row0 + j; r[j] = rr < NN ? rr : NN - 1; }

    float acc[4][4] = {};
    #pragma unroll 2
    for (int k = 0; k < K1; k += 4) {
        float a[4][4];
        #pragma unroll
        for (int j = 0; j < 4; j++)
            *(float4*)a[j] = *(const float4*)(A1 + (size_t)r[j] * K1 + k);
        #pragma unroll
        for (int kk = 0; kk < 4; kk++) {
            float w[4];
            *(float4*)w = *(const float4*)&Ws[(k + kk) * C + cg * 4];
            #pragma unroll
            for (int j = 0; j < 4; j++)
                #pragma unroll
                for (int c = 0; c < 4; c++)
                    acc[j][c] = fmaf(a[j][kk], w[c], acc[j][c]);
        }
    }
    #pragma unroll
    for (int j = 0; j < 4; j++) {
        int rr = row0 + j;
        if (rr >= NN) break;
        float s = rowscale[rr];
        __half2 h0 = __floats2half2_rn(acc[j][0] * s, acc[j][1] * s);
        __half2 h1 = __floats2half2_rn(acc[j][2] * s, acc[j][3] * s);
        __half2* p = (__half2*)(outh + (size_t)rr * C + cg * 4);
        p[0] = h0; p[1] = h1;
    }
}

// ---------------- fp32 gathers (hyper chain) ---------------------------------------
#define ACC4(acc, v) { acc.x += v.x; acc.y += v.y; acc.z += v.z; acc.w += v.w; }
#define GLOOP8(CSR, SRC, PITCH)                                                    \
    float4 acc = make_float4(0.f, 0.f, 0.f, 0.f);                                  \
    float4 ac2 = make_float4(0.f, 0.f, 0.f, 0.f);                                  \
    int i = s;                                                                     \
    for (; i + 7 < e; i += 8) {                                                    \
        int n0 = CSR[i],     n1 = CSR[i + 1], n2 = CSR[i + 2], n3 = CSR[i + 3];    \
        int n4 = CSR[i + 4], n5 = CSR[i + 5], n6 = CSR[i + 6], n7 = CSR[i + 7];    \
        float4 v0 = *(const float4*)(SRC + (size_t)n0 * PITCH + l * 4);            \
        float4 v1 = *(const float4*)(SRC + (size_t)n1 * PITCH + l * 4);            \
        float4 v2 = *(const float4*)(SRC + (size_t)n2 * PITCH + l * 4);            \
        float4 v3 = *(const float4*)(SRC + (size_t)n3 * PITCH + l * 4);            \
        float4 v4 = *(const float4*)(SRC + (size_t)n4 * PITCH + l * 4);            \
        float4 v5 = *(const float4*)(SRC + (size_t)n5 * PITCH + l * 4);            \
        float4 v6 = *(const float4*)(SRC + (size_t)n6 * PITCH + l * 4);            \
        float4 v7 = *(const float4*)(SRC + (size_t)n7 * PITCH + l * 4);            \
        ACC4(acc, v0); ACC4(ac2, v1); ACC4(acc, v2); ACC4(ac2, v3);                \
        ACC4(acc, v4); ACC4(ac2, v5); ACC4(acc, v6); ACC4(ac2, v7);                \
    }                                                                              \
    for (; i + 3 < e; i += 4) {                                                    \
        int n0 = CSR[i], n1 = CSR[i + 1], n2 = CSR[i + 2], n3 = CSR[i + 3];        \
        float4 v0 = *(const float4*)(SRC + (size_t)n0 * PITCH + l * 4);            \
        float4 v1 = *(const float4*)(SRC + (size_t)n1 * PITCH + l * 4);            \
        float4 v2 = *(const float4*)(SRC + (size_t)n2 * PITCH + l * 4);            \
        float4 v3 = *(const float4*)(SRC + (size_t)n3 * PITCH + l * 4);            \
        ACC4(acc, v0); ACC4(ac2, v1); ACC4(acc, v2); ACC4(ac2, v3);                \
    }                                                                              \
    for (; i < e; i++) {                                                           \
        int n0 = CSR[i];                                                           \
        float4 v0 = *(const float4*)(SRC + (size_t)n0 * PITCH + l * 4);            \
        ACC4(acc, v0);                                                             \
    }                                                                              \
    acc.x += ac2.x; acc.y += ac2.y; acc.z += ac2.z; acc.w += ac2.w;

__global__ void k_gath_he(const float* __restrict__ xw) {
    int t = blockIdx.x * blockDim.x + threadIdx.x;
    int he = t >> 4, l = t & 15;
    if (he >= HEN) return;
    int s = g_offH[he], e = g_offH[he + 1];
    GLOOP8(g_csrHn, xw, D)
    float b = g_Binv[he];
    acc.x *= b; acc.y *= b; acc.z *= b; acc.w *= b;
    *(float4*)(g_ef + (size_t)he * D + l * 4) = acc;
}

__global__ void k_gath_e2n(const float* __restrict__ bias, float* __restrict__ out, int relu) {
    int t = blockIdx.x * blockDim.x + threadIdx.x;
    int node = t >> 4, l = t & 15;
    if (node >= NN) return;
    int s = g_offN[node], e = g_offN[node + 1];
    GLOOP8(g_csrNh, g_ef, D)
    float dv = g_Dninv[node];
    float4 bb = *(const float4*)(bias + l * 4);
    float4 o;
    o.x = dv * acc.x + bb.x; o.y = dv * acc.y + bb.y;
    o.z = dv * acc.z + bb.z; o.w = dv * acc.w + bb.w;
    if (relu) {
        o.x = fmaxf(o.x, 0.f); o.y = fmaxf(o.y, 0.f);
        o.z = fmaxf(o.z, 0.f); o.w = fmaxf(o.w, 0.f);
    }
    *(float4*)(out + (size_t)node * D + l * 4) = o;
}

// ---------------- fp16 gathers (GCN chain) -----------------------------------------
__device__ __forceinline__ void hacc8(float* a, uint4 v) {
    float2 a0 = __half22float2(*(__half2*)&v.x);
    float2 a1 = __half22float2(*(__half2*)&v.y);
    float2 a2 = __half22float2(*(__half2*)&v.z);
    float2 a3 = __half22float2(*(__half2*)&v.w);
    a[0] += a0.x; a[1] += a0.y; a[2] += a1.x; a[3] += a1.y;
    a[4] += a2.x; a[5] += a2.y; a[6] += a3.x; a[7] += a3.y;
}
#define HLOOP4(CSR, SRCB, ROWB)                                                    \
    float acc[8] = {};                                                             \
    float ac2[8] = {};                                                             \
    int i = s;                                                                     \
    for (; i + 3 < e; i += 4) {                                                    \
        int n0 = CSR[i], n1 = CSR[i + 1], n2 = CSR[i + 2], n3 = CSR[i + 3];        \
        uint4 v0 = *(const uint4*)(SRCB + (size_t)n0 * ROWB + l * 16);             \
        uint4 v1 = *(const uint4*)(SRCB + (size_t)n1 * ROWB + l * 16);             \
        uint4 v2 = *(const uint4*)(SRCB + (size_t)n2 * ROWB + l * 16);             \
        uint4 v3 = *(const uint4*)(SRCB + (size_t)n3 * ROWB + l * 16);             \
        hacc8(acc, v0); hacc8(ac2, v1); hacc8(acc, v2); hacc8(ac2, v3);            \
    }                                                                              \
    for (; i < e; i++) {                                                           \
        int n0 = CSR[i];                                                           \
        uint4 v0 = *(const uint4*)(SRCB + (size_t)n0 * ROWB + l * 16);             \
        hacc8(acc, v0);                                                            \
    }                                                                              \
    _Pragma("unroll")                                                              \
    for (int q = 0; q < 8; q++) acc[q] += ac2[q];

// gcn1: 8 lanes/node over fp16 xwd rows (128B); writes fp32 xg
__global__ void k_gcn64h(const float* __restrict__ bias, float* __restrict__ out) {
    int t = blockIdx.x * blockDim.x + threadIdx.x;
    int node = t >> 3, l = t & 7;
    if (node >= NN) return;
    int s = g_offE[node], e = g_offE[node + 1];
    const char* src = (const char*)g_xwh;
    HLOOP4(g_csrE, src, 128)
    uint4 sv = *(const uint4*)(src + (size_t)node * 128 + l * 16);
    float slf[8] = {};
    hacc8(slf, sv);
    float ds = g_dis[node];
    float4 b0 = *(const float4*)(bias + l * 8);
    float4 b1 = *(const float4*)(bias + l * 8 + 4);
    float o[8];
    #pragma unroll
    for (int q = 0; q < 8; q++) o[q] = ds * (acc[q] + slf[q]);
    o[0] += b0.x; o[1] += b0.y; o[2] += b0.z; o[3] += b0.w;
    o[4] += b1.x; o[5] += b1.y; o[6] += b1.z; o[7] += b1.w;
    #pragma unroll
    for (int q = 0; q < 8; q++) o[q] = fmaxf(o[q], 0.f);
    float* dst = out + (size_t)node * D + l * 8;
    *(float4*)dst = make_float4(o[0], o[1], o[2], o[3]);
    *(float4*)(dst + 4) = make_float4(o[4], o[5], o[6], o[7]);
}

// gcn2 + folded head: 5 lanes/node over fp16 t40 rows (80B); writes FINAL fp32 out
__global__ void k_gcn40h(float* __restrict__ out) {
    int t = blockIdx.x * blockDim.x + threadIdx.x;
    int node = t / 5, l = t % 5;
    if (node >= NN) return;
    int s = g_offE[node], e = g_offE[node + 1];
    const char* src = (const char*)g_t40h;
    HLOOP4(g_csrE, src, 80)
    uint4 sv = *(const uint4*)(src + (size_t)node * 80 + l * 16);
    float slf[8] = {};
    hacc8(slf, sv);
    float ds = g_dis[node];
    float4 b0 = *(const float4*)(g_bp + l * 8);
    float4 b1 = *(const float4*)(g_bp + l * 8 + 4);
    float o[8];
    #pragma unroll
    for (int q = 0; q < 8; q++) o[q] = ds * (acc[q] + slf[q]);
    o[0] += b0.x; o[1] += b0.y; o[2] += b0.z; o[3] += b0.w;
    o[4] += b1.x; o[5] += b1.y; o[6] += b1.z; o[7] += b1.w;
    float* dst = out + (size_t)node * NC + l * 8;
    *(float4*)dst = make_float4(o[0], o[1], o[2], o[3]);
    *(float4*)(dst + 4) = make_float4(o[4], o[5], o[6], o[7]);
}

// ---------------- launch (single stream) ----------------
extern "C" void kernel_launch(void* const* d_in, const int* in_sizes, int n_in,
                              void* d_out, int out_size) {
    const float* x    = (const float*)d_in[0];
    const void*  eidx = d_in[1];
    const void*  hidx = d_in[2];
    const float* W_h1 = (const float*)d_in[3];
    const float* b_h1 = (const float*)d_in[4];
    const float* W_h2 = (const float*)d_in[5];
    const float* b_h2 = (const float*)d_in[6];
    const float* W_c1 = (const float*)d_in[7];
    const float* b_c1 = (const float*)d_in[8];
    const float* W_c2 = (const float*)d_in[9];
    const float* b_c2 = (const float*)d_in[10];
    const float* W_lp = (const float*)d_in[11];
    const float* b_lp = (const float*)d_in[12];
    float* out = (float*)d_out;

    float *p_xw, *p_h1, *p_h2, *p_xg, *p_dis, *p_Wp;
    __half *p_xwh, *p_t40h;
    cudaGetSymbolAddress((void**)&p_xw,   g_xw);
    cudaGetSymbolAddress((void**)&p_h1,   g_h1);
    cudaGetSymbolAddress((void**)&p_h2,   g_h2);
    cudaGetSymbolAddress((void**)&p_xg,   g_xg);
    cudaGetSymbolAddress((void**)&p_dis,  g_dis);
    cudaGetSymbolAddress((void**)&p_Wp,   g_Wp);
    cudaGetSymbolAddress((void**)&p_xwh,  g_xwh);
    cudaGetSymbolAddress((void**)&p_t40h, g_t40h);

    const int B = 256;
    const int GR  = (NN + 63) / 64;
    const int GRM = (NN + 127) / 128;

    const int SH128 = 2 * 64 * padw(128 / 2) * 4;   // 34816
    const int SH64  = 2 * 64 * padw(64 / 2) * 4;    // 18432
    const int SH192 = 2 * 64 * padw(192 / 2) * 4;   // 51200
    cudaFuncSetAttribute(k_mma<D, 0>,     cudaFuncAttributeMaxDynamicSharedMemorySize, SH64);
    cudaFuncSetAttribute(k_mma_h<FIN, D>, cudaFuncAttributeMaxDynamicSharedMemorySize, SH192);
    cudaFuncSetAttribute(k_fill_gemm,     cudaFuncAttributeMaxDynamicSharedMemorySize, SH128);

    // ---- CSR build (GEMM1 fused into fill) ----
    k_cnt<<<(EE + B - 1) / B, B>>>(eidx, hidx);
    k_scan1f<<<dim3((NN + 1023) / 1024, 4), 256>>>(W_c2, b_c2, W_lp, b_lp);
    k_scan3f<<<dim3((NN + 255) / 256, 3), 256>>>();
    k_fill_gemm<<<GEMM_BLKS + (EE + B - 1) / B, B, SH128>>>(eidx, hidx, x, W_h1, p_xw);

    // ---- hyperconv 1 ----
    k_gath_he<<<(HEN * 16 + B - 1) / B, B>>>(p_xw);
    k_gath_e2n<<<(NN * 16 + B - 1) / B, B>>>(b_h1, p_h1, 1);

    // ---- hyperconv 2 ----
    k_mma<D, 0><<<GRM, 128, SH64>>>(p_h1, nullptr, W_h2, p_xw, nullptr);
    k_gath_he<<<(HEN * 16 + B - 1) / B, B>>>(p_xw);
    k_gath_e2n<<<(NN * 16 + B - 1) / B, B>>>(b_h2, p_h2, 0);

    // ---- gcn 1 (concat input, dis-prescaled, fp16 xwd) ----
    k_mma_h<FIN, D><<<GRM, 128, SH192>>>(x, p_h2, W_c1, p_xwh, p_dis);
    k_gcn64h<<<(NN * 8 + B - 1) / B, B>>>(b_c1, p_xg);

    // ---- gcn 2 with folded head (fp16 t40) ----
    k_gemm_h<D, NC><<<GR, 160>>>(p_xg, p_Wp, p_t40h, p_dis);
    k_gcn40h<<<(NN * 5 + 319) / 320, 320>>>(out);
}

// round 17
// speedup vs baseline: 1.0617x; 1.0432x over previous
#include <cuda_runtime.h>
#include <cuda_bf16.h>
#include <cuda_fp16.h>
#include <cstdint>

#define NN  100000
#define EE  1600000
#define PP  800000
#define HEN 20000
#define FIN 128
#define D   64
#define NC  40

// ---------------- scratch (device globals; no allocation allowed) ----------------
__device__ float  g_h1 [NN * D];
__device__ float  g_h2 [NN * D];
__device__ float  g_xg [NN * D];
__device__ __half g_xwh[NN * D];     // gemm outputs (gather source, fp16)
__device__ __half g_efh[HEN * D];    // hyperedge features (gather source, fp16)
__device__ __half g_t40h[NN * NC];   // gcn2 xwd (gather source, fp16)
__device__ float  g_dis  [NN];
__device__ float  g_Dninv[NN];
__device__ float  g_Binv [HEN];
__device__ float  g_Wp[D * NC];      // W_c2 @ W_lp
__device__ float  g_bp[NC];          // b_c2 @ W_lp + b_lp
__device__ int g_cntE[NN], g_cntH[HEN], g_cntN[NN];   // static zero-init; re-zeroed in fill
__device__ int g_offE[NN + 1], g_offH[HEN + 1], g_offN[NN + 1];
__device__ int g_curE[NN], g_curH[HEN], g_curN[NN];
__device__ int g_csrE[EE];
__device__ int g_csrHn[PP];
__device__ int g_csrNh[PP];
__device__ int g_bsum[512];

// ---------------- helpers ----------------
__device__ __forceinline__ int sniff64(const void* b) {
    int acc = 0;
    #pragma unroll
    for (int i = 0; i < 8; i++) acc |= ((const int*)b)[2 * i + 1];
    return acc == 0;
}
__device__ __forceinline__ long long ldidx(const void* b, long long i, int m64) {
    return m64 ? ((const long long*)b)[i] : (long long)((const int*)b)[i];
}

// ---------------- fused counting ----------------
__global__ void k_cnt(const void* eidx, const void* hidx) {
    int me = sniff64(eidx), mh = sniff64(hidx);
    int i = blockIdx.x * blockDim.x + threadIdx.x;
    if (i < EE) {
        int dst = (int)ldidx(eidx, (long long)EE + i, me);
        atomicAdd(&g_cntE[dst], 1);
    }
    if (i < PP) {
        int node = (int)ldidx(hidx, i, mh);
        int he   = (int)ldidx(hidx, (long long)PP + i, mh);
        atomicAdd(&g_cntN[node], 1);
        atomicAdd(&g_cntH[he], 1);
    }
}

// ---------------- scan stage 1 (y: 0=E,1=N,2=H; y==3: W_lp fold) --------------------
__global__ void k_scan1f(const float* __restrict__ W_c2, const float* __restrict__ b_c2,
                         const float* __restrict__ W_lp, const float* __restrict__ b_lp) {
    int t = threadIdx.x;
    if (blockIdx.y == 3) {
        if (blockIdx.x != 0) return;
        for (int i = t; i < D * NC + NC; i += 256) {
            if (i < D * NC) {
                int k = i / NC, c = i - k * NC;
                float s = 0.f;
                #pragma unroll
                for (int j = 0; j < NC; j++) s = fmaf(W_c2[k * NC + j], W_lp[j * NC + c], s);
                g_Wp[i] = s;
            } else {
                int c = i - D * NC;
                float s = b_lp[c];
                #pragma unroll
                for (int j = 0; j < NC; j++) s = fmaf(b_c2[j], W_lp[j * NC + c], s);
                g_bp[c] = s;
            }
        }
        return;
    }
    const int* cnt; int n; int* excl; int* bs;
    if (blockIdx.y == 0)      { cnt = g_cntE; n = NN;  excl = g_offE; bs = g_bsum;       }
    else if (blockIdx.y == 1) { cnt = g_cntN; n = NN;  excl = g_offN; bs = g_bsum + 128; }
    else                      { cnt = g_cntH; n = HEN; excl = g_offH; bs = g_bsum + 256; }
    __shared__ int wsum[8];
    int base = blockIdx.x * 1024 + t * 4;
    int v0 = 0, v1 = 0, v2 = 0, v3 = 0;
    if (base + 0 < n) v0 = cnt[base + 0];
    if (base + 1 < n) v1 = cnt[base + 1];
    if (base + 2 < n) v2 = cnt[base + 2];
    if (base + 3 < n) v3 = cnt[base + 3];
    int tot = v0 + v1 + v2 + v3;
    int lane = t & 31, w = t >> 5;
    int p = tot;
    for (int d = 1; d < 32; d <<= 1) { int u = __shfl_up_sync(~0u, p, d); if (lane >= d) p += u; }
    if (lane == 31) wsum[w] = p;
    __syncthreads();
    int wb = 0;
    for (int i = 0; i < w; i++) wb += wsum[i];
    int e0 = wb + p - tot;
    if (base + 0 < n) excl[base + 0] = e0;
    if (base + 1 < n) excl[base + 1] = e0 + v0;
    if (base + 2 < n) excl[base + 2] = e0 + v0 + v1;
    if (base + 3 < n) excl[base + 3] = e0 + v0 + v1 + v2;
    if (t == 255) bs[blockIdx.x] = wb + p;
}

// ---------------- scan stage 2+3 fused (block-base via in-block reduce) -------------
__global__ void k_scan3f() {
    __shared__ int sred[256];
    int t = threadIdx.x;
    int y = blockIdx.y;
    int i = blockIdx.x * 256 + t;
    int c = (blockIdx.x * 256) >> 10;
    const int* bs = g_bsum + (y == 0 ? 0 : (y == 1 ? 128 : 256));
    sred[t] = (t < c) ? bs[t] : 0;
    __syncthreads();
    #pragma unroll
    for (int st = 128; st > 0; st >>= 1) {
        if (t < st) sred[t] += sred[t + st];
        __syncthreads();
    }
    int S = sred[0];
    if (y == 0) {
        if (i < NN) {
            int v = g_offE[i] + S;
            g_offE[i] = v; g_curE[i] = v;
            g_dis[i] = rsqrtf((float)g_cntE[i] + 1.0f);
            int dn = g_cntN[i];
            g_Dninv[i] = dn > 0 ? 1.0f / (float)dn : 0.0f;
        }
        if (i < HEN) {
            int bh = g_cntH[i];
            g_Binv[i] = bh > 0 ? 1.0f / (float)bh : 0.0f;
        }
        if (i == 0) g_offE[NN] = EE;
    } else if (y == 1) {
        if (i < NN) {
            int v = g_offN[i] + S;
            g_offN[i] = v; g_curN[i] = v;
        }
        if (i == 0) g_offN[NN] = PP;
    } else {
        if (i < HEN) {
            int v = g_offH[i] + S;
            g_offH[i] = v; g_curH[i] = v;
        }
        if (i == 0) g_offH[HEN] = PP;
    }
}

// ---------------- bf16 split tensor-core GEMM body (C=64, fp16 out) -----------------
__host__ __device__ constexpr int padw(int v) { int r = v % 32; return v + ((r <= 4) ? (4 - r) : (36 - r)); }

__device__ __forceinline__ void bsplit(float2 q, uint32_t& hi, uint32_t& lo) {
    uint32_t h;
    asm("cvt.rn.bf16x2.f32 %0, %1, %2;" : "=r"(h) : "f"(q.y), "f"(q.x));
    float hx = __uint_as_float(h << 16);
    float hy = __uint_as_float(h & 0xffff0000u);
    float rx = q.x - hx, ry = q.y - hy;
    uint32_t l;
    asm("cvt.rn.bf16x2.f32 %0, %1, %2;" : "=r"(l) : "f"(ry), "f"(rx));
    hi = h; lo = l;
}
#define MMA16816(c, a, b0, b1)                                                     \
    asm volatile("mma.sync.aligned.m16n8k16.row.col.f32.bf16.bf16.f32 "            \
                 "{%0,%1,%2,%3}, {%4,%5,%6,%7}, {%8,%9}, {%0,%1,%2,%3};"           \
                 : "+f"(c[0]), "+f"(c[1]), "+f"(c[2]), "+f"(c[3])                  \
                 : "r"(a[0]), "r"(a[1]), "r"(a[2]), "r"(a[3]), "r"(b0), "r"(b1))

template<int K1, int K2, int WARPS>
__device__ __forceinline__ void gemm_body(
    const float* __restrict__ A1, const float* __restrict__ A2,
    const float* __restrict__ W, __half* __restrict__ outh,
    const float* __restrict__ rowscale, int bx)
{
    constexpr int KT = K1 + K2;
    constexpr int C = 64;
    constexpr int KPW = padw(KT / 2);
    constexpr int KPE = KPW * 2;
    extern __shared__ unsigned char smraw[];
    __nv_bfloat16* WtHi = (__nv_bfloat16*)smraw;
    __nv_bfloat16* WtLo = WtHi + C * KPE;

    int tid = threadIdx.x;
    for (int idx = tid; idx < KT * C; idx += WARPS * 32) {
        int k = idx >> 6, n = idx & 63;
        float w = W[idx];
        __nv_bfloat16 h = __float2bfloat16(w);
        float lo = w - __bfloat162float(h);
        WtHi[n * KPE + k] = h;
        WtLo[n * KPE + k] = __float2bfloat16(lo);
    }
    __syncthreads();

    const uint32_t* WH = (const uint32_t*)WtHi;
    const uint32_t* WL = (const uint32_t*)WtLo;

    int w = tid >> 5, lane = tid & 31;
    int g = lane >> 2, t = lane & 3;
    int m0 = bx * (WARPS * 32) + w * 32;
    int rows[4] = { m0 + g, m0 + g + 8, m0 + 16 + g, m0 + 24 + g };
    int rc[4];
    #pragma unroll
    for (int i = 0; i < 4; i++) rc[i] = rows[i] < NN ? rows[i] : NN - 1;

    float acc[2][8][4] = {};

    for (int kc = 0; kc < KT / 16; kc++) {
        int kk = kc * 16;
        uint32_t ah[2][4], al[2][4];
        #pragma unroll
        for (int f = 0; f < 2; f++) {
            const float *p0, *p1;
            if (K2 == 0 || kk < K1) {
                p0 = A1 + (size_t)rc[2 * f] * K1 + kk;
                p1 = A1 + (size_t)rc[2 * f + 1] * K1 + kk;
            } else {
                p0 = A2 + (size_t)rc[2 * f] * K2 + (kk - K1);
                p1 = A2 + (size_t)rc[2 * f + 1] * K2 + (kk - K1);
            }
            float2 q0 = *(const float2*)(p0 + 2 * t);
            float2 q1 = *(const float2*)(p1 + 2 * t);
            float2 q2 = *(const float2*)(p0 + 2 * t + 8);
            float2 q3 = *(const float2*)(p1 + 2 * t + 8);
            bsplit(q0, ah[f][0], al[f][0]);
            bsplit(q1, ah[f][1], al[f][1]);
            bsplit(q2, ah[f][2], al[f][2]);
            bsplit(q3, ah[f][3], al[f][3]);
        }
        #pragma unroll
        for (int s = 0; s < 8; s++) {
            int wi = (s * 8 + g) * KPW + kc * 8 + t;
            uint32_t bh0 = WH[wi], bh1 = WH[wi + 4];
            uint32_t bl0 = WL[wi], bl1 = WL[wi + 4];
            #pragma unroll
            for (int f = 0; f < 2; f++) {
                MMA16816(acc[f][s], ah[f], bh0, bh1);
                MMA16816(acc[f][s], al[f], bh0, bh1);
                MMA16816(acc[f][s], ah[f], bl0, bl1);
            }
        }
    }

    float rs[4] = {1.f, 1.f, 1.f, 1.f};
    if (rowscale) {
        #pragma unroll
        for (int i = 0; i < 4; i++) rs[i] = rowscale[rc[i]];
    }
    #pragma unroll
    for (int f = 0; f < 2; f++) {
        #pragma unroll
        for (int s = 0; s < 8; s++) {
            int col = s * 8 + 2 * t;
            int ra = rows[2 * f], rb = rows[2 * f + 1];
            if (ra < NN)
                *(__half2*)(outh + (size_t)ra * 64 + col) =
                    __floats2half2_rn(acc[f][s][0] * rs[2 * f], acc[f][s][1] * rs[2 * f]);
            if (rb < NN)
                *(__half2*)(outh + (size_t)rb * 64 + col) =
                    __floats2half2_rn(acc[f][s][2] * rs[2 * f + 1], acc[f][s][3] * rs[2 * f + 1]);
        }
    }
}

template<int K1, int K2>
__global__ void k_mma_h(const float* __restrict__ A1, const float* __restrict__ A2,
                        const float* __restrict__ W, __half* __restrict__ outh,
                        const float* __restrict__ rowscale) {
    gemm_body<K1, K2, 4>(A1, A2, W, outh, rowscale, blockIdx.x);
}

// ---------------- fused: CSR fill + GEMM1 (x@W_h1 -> fp16) in one launch -----------
#define GEMM_BLKS ((NN + 255) / 256)
__global__ void k_fill_gemm(const void* eidx, const void* hidx,
                            const float* __restrict__ x, const float* __restrict__ W,
                            __half* __restrict__ xwh) {
    if (blockIdx.x < GEMM_BLKS) {
        gemm_body<FIN, 0, 8>(x, nullptr, W, xwh, nullptr, blockIdx.x);
        return;
    }
    int bid = blockIdx.x - GEMM_BLKS;
    int me = sniff64(eidx), mh = sniff64(hidx);
    int i = bid * blockDim.x + threadIdx.x;
    if (i < EE) {
        int src = (int)ldidx(eidx, i, me);
        int dst = (int)ldidx(eidx, (long long)EE + i, me);
        int pos = atomicAdd(&g_curE[dst], 1);
        g_csrE[pos] = src;
    }
    if (i < PP) {
        int node = (int)ldidx(hidx, i, mh);
        int he   = (int)ldidx(hidx, (long long)PP + i, mh);
        int p1 = atomicAdd(&g_curH[he], 1);   g_csrHn[p1] = node;
        int p2 = atomicAdd(&g_curN[node], 1); g_csrNh[p2] = he;
    }
    if (i < NN) { g_cntE[i] = 0; g_cntN[i] = 0; }
    if (i < HEN) g_cntH[i] = 0;
}

// ---------------- FFMA GEMM (C=40, fp16 out): t40h = rowscale*(A@W) ----------------
template<int K1, int C>
__global__ void k_gemm_h(const float* __restrict__ A1, const float* __restrict__ W,
                         __half* __restrict__ outh, const float* __restrict__ rowscale) {
    constexpr int CG = C / 4;
    __shared__ float Ws[K1 * C];
    int tid = threadIdx.x;
    for (int i = tid; i < K1 * C; i += CG * 16) Ws[i] = W[i];
    __syncthreads();
    int cg = tid % CG, rg = tid / CG;
    int row0 = blockIdx.x * 64 + rg * 4;
    int r[4];
    #pragma unroll
    for (int j = 0; j < 4; j++) { int rr = row0 + j; r[j] = rr < NN ? rr : NN - 1; }

    float acc[4][4] = {};
    #pragma unroll 2
    for (int k = 0; k < K1; k += 4) {
        float a[4][4];
        #pragma unroll
        for (int j = 0; j < 4; j++)
            *(float4*)a[j] = *(const float4*)(A1 + (size_t)r[j] * K1 + k);
        #pragma unroll
        for (int kk = 0; kk < 4; kk++) {
            float w[4];
            *(float4*)w = *(const float4*)&Ws[(k + kk) * C + cg * 4];
            #pragma unroll
            for (int j = 0; j < 4; j++)
                #pragma unroll
                for (int c = 0; c < 4; c++)
                    acc[j][c] = fmaf(a[j][kk], w[c], acc[j][c]);
        }
    }
    #pragma unroll
    for (int j = 0; j < 4; j++) {
        int rr = row0 + j;
        if (rr >= NN) break;
        float s = rowscale[rr];
        __half2 h0 = __floats2half2_rn(acc[j][0] * s, acc[j][1] * s);
        __half2 h1 = __floats2half2_rn(acc[j][2] * s, acc[j][3] * s);
        __half2* p = (__half2*)(outh + (size_t)rr * C + cg * 4);
        p[0] = h0; p[1] = h1;
    }
}

// ---------------- fp16 gathers (8 loads in flight, dual accumulators) ---------------
__device__ __forceinline__ void hacc8(float* a, uint4 v) {
    float2 a0 = __half22float2(*(__half2*)&v.x);
    float2 a1 = __half22float2(*(__half2*)&v.y);
    float2 a2 = __half22float2(*(__half2*)&v.z);
    float2 a3 = __half22float2(*(__half2*)&v.w);
    a[0] += a0.x; a[1] += a0.y; a[2] += a1.x; a[3] += a1.y;
    a[4] += a2.x; a[5] += a2.y; a[6] += a3.x; a[7] += a3.y;
}
#define HLOOP8(CSR, SRCB, ROWB)                                                    \
    float acc[8] = {};                                                             \
    float ac2[8] = {};                                                             \
    int i = s;                                                                     \
    for (; i + 7 < e; i += 8) {                                                    \
        int n0 = CSR[i],     n1 = CSR[i + 1], n2 = CSR[i + 2], n3 = CSR[i + 3];    \
        int n4 = CSR[i + 4], n5 = CSR[i + 5], n6 = CSR[i + 6], n7 = CSR[i + 7];    \
        uint4 v0 = *(const uint4*)(SRCB + (size_t)n0 * ROWB + l * 16);             \
        uint4 v1 = *(const uint4*)(SRCB + (size_t)n1 * ROWB + l * 16);             \
        uint4 v2 = *(const uint4*)(SRCB + (size_t)n2 * ROWB + l * 16);             \
        uint4 v3 = *(const uint4*)(SRCB + (size_t)n3 * ROWB + l * 16);             \
        uint4 v4 = *(const uint4*)(SRCB + (size_t)n4 * ROWB + l * 16);             \
        uint4 v5 = *(const uint4*)(SRCB + (size_t)n5 * ROWB + l * 16);             \
        uint4 v6 = *(const uint4*)(SRCB + (size_t)n6 * ROWB + l * 16);             \
        uint4 v7 = *(const uint4*)(SRCB + (size_t)n7 * ROWB + l * 16);             \
        hacc8(acc, v0); hacc8(ac2, v1); hacc8(acc, v2); hacc8(ac2, v3);            \
        hacc8(acc, v4); hacc8(ac2, v5); hacc8(acc, v6); hacc8(ac2, v7);            \
    }                                                                              \
    for (; i + 3 < e; i += 4) {                                                    \
        int n0 = CSR[i], n1 = CSR[i + 1], n2 = CSR[i + 2], n3 = CSR[i + 3];        \
        uint4 v0 = *(const uint4*)(SRCB + (size_t)n0 * ROWB + l * 16);             \
        uint4 v1 = *(const uint4*)(SRCB + (size_t)n1 * ROWB + l * 16);             \
        uint4 v2 = *(const uint4*)(SRCB + (size_t)n2 * ROWB + l * 16);             \
        uint4 v3 = *(const uint4*)(SRCB + (size_t)n3 * ROWB + l * 16);             \
        hacc8(acc, v0); hacc8(ac2, v1); hacc8(acc, v2); hacc8(ac2, v3);            \
    }                                                                              \
    for (; i < e; i++) {                                                           \
        int n0 = CSR[i];                                                           \
        uint4 v0 = *(const uint4*)(SRCB + (size_t)n0 * ROWB + l * 16);             \
        hacc8(acc, v0);                                                            \
    }                                                                              \
    _Pragma("unroll")                                                              \
    for (int q = 0; q < 8; q++) acc[q] += ac2[q];

// he gather: fp16 xw -> fp16 ef (8 lanes/hyperedge)
__global__ void k_gath_he(void) {
    int t = blockIdx.x * blockDim.x + threadIdx.x;
    int he = t >> 3, l = t & 7;
    if (he >= HEN) return;
    int s = g_offH[he], e = g_offH[he + 1];
    const char* src = (const char*)g_xwh;
    HLOOP8(g_csrHn, src, 128)
    float b = g_Binv[he];
    __half2 h[4];
    #pragma unroll
    for (int q = 0; q < 4; q++)
        h[q] = __floats2half2_rn(acc[2 * q] * b, acc[2 * q + 1] * b);
    *(uint4*)((char*)g_efh + (size_t)he * 128 + l * 16) = *(uint4*)h;
}

// e2n gather: fp16 ef -> fp32 out (8 lanes/node)
__global__ void k_gath_e2n(const float* __restrict__ bias, float* __restrict__ out, int relu) {
    int t = blockIdx.x * blockDim.x + threadIdx.x;
    int node = t >> 3, l = t & 7;
    if (node >= NN) return;
    int s = g_offN[node], e = g_offN[node + 1];
    const char* src = (const char*)g_efh;
    HLOOP8(g_csrNh, src, 128)
    float dv = g_Dninv[node];
    float4 b0 = *(const float4*)(bias + l * 8);
    float4 b1 = *(const float4*)(bias + l * 8 + 4);
    float o[8];
    #pragma unroll
    for (int q = 0; q < 8; q++) o[q] = dv * acc[q];
    o[0] += b0.x; o[1] += b0.y; o[2] += b0.z; o[3] += b0.w;
    o[4] += b1.x; o[5] += b1.y; o[6] += b1.z; o[7] += b1.w;
    if (relu) {
        #pragma unroll
        for (int q = 0; q < 8; q++) o[q] = fmaxf(o[q], 0.f);
    }
    float* dst = out + (size_t)node * D + l * 8;
    *(float4*)dst = make_float4(o[0], o[1], o[2], o[3]);
    *(float4*)(dst + 4) = make_float4(o[4], o[5], o[6], o[7]);
}

// gcn1: fp16 xwd -> fp32 xg (8 lanes/node)
__global__ void k_gcn64h(const float* __restrict__ bias, float* __restrict__ out) {
    int t = blockIdx.x * blockDim.x + threadIdx.x;
    int node = t >> 3, l = t & 7;
    if (node >= NN) return;
    int s = g_offE[node], e = g_offE[node + 1];
    const char* src = (const char*)g_xwh;
    HLOOP8(g_csrE, src, 128)
    uint4 sv = *(const uint4*)(src + (size_t)node * 128 + l * 16);
    float slf[8] = {};
    hacc8(slf, sv);
    float ds = g_dis[node];
    float4 b0 = *(const float4*)(bias + l * 8);
    float4 b1 = *(const float4*)(bias + l * 8 + 4);
    float o[8];
    #pragma unroll
    for (int q = 0; q < 8; q++) o[q] = ds * (acc[q] + slf[q]);
    o[0] += b0.x; o[1] += b0.y; o[2] += b0.z; o[3] += b0.w;
    o[4] += b1.x; o[5] += b1.y; o[6] += b1.z; o[7] += b1.w;
    #pragma unroll
    for (int q = 0; q < 8; q++) o[q] = fmaxf(o[q], 0.f);
    float* dst = out + (size_t)node * D + l * 8;
    *(float4*)dst = make_float4(o[0], o[1], o[2], o[3]);
    *(float4*)(dst + 4) = make_float4(o[4], o[5], o[6], o[7]);
}

// gcn2 + folded head: fp16 t40 -> FINAL fp32 out (5 lanes/node)
__global__ void k_gcn40h(float* __restrict__ out) {
    int t = blockIdx.x * blockDim.x + threadIdx.x;
    int node = t / 5, l = t % 5;
    if (node >= NN) return;
    int s = g_offE[node], e = g_offE[node + 1];
    const char* src = (const char*)g_t40h;
    HLOOP8(g_csrE, src, 80)
    uint4 sv = *(const uint4*)(src + (size_t)node * 80 + l * 16);
    float slf[8] = {};
    hacc8(slf, sv);
    float ds = g_dis[node];
    float4 b0 = *(const float4*)(g_bp + l * 8);
    float4 b1 = *(const float4*)(g_bp + l * 8 + 4);
    float o[8];
    #pragma unroll
    for (int q = 0; q < 8; q++) o[q] = ds * (acc[q] + slf[q]);
    o[0] += b0.x; o[1] += b0.y; o[2] += b0.z; o[3] += b0.w;
    o[4] += b1.x; o[5] += b1.y; o[6] += b1.z; o[7] += b1.w;
    float* dst = out + (size_t)node * NC + l * 8;
    *(float4*)dst = make_float4(o[0], o[1], o[2], o[3]);
    *(float4*)(dst + 4) = make_float4(o[4], o[5], o[6], o[7]);
}

// ---------------- launch (single stream) ----------------
extern "C" void kernel_launch(void* const* d_in, const int* in_sizes, int n_in,
                              void* d_out, int out_size) {
    const float* x    = (const float*)d_in[0];
    const void*  eidx = d_in[1];
    const void*  hidx = d_in[2];
    const float* W_h1 = (const float*)d_in[3];
    const float* b_h1 = (const float*)d_in[4];
    const float* W_h2 = (const float*)d_in[5];
    const float* b_h2 = (const float*)d_in[6];
    const float* W_c1 = (const float*)d_in[7];
    const float* b_c1 = (const float*)d_in[8];
    const float* W_c2 = (const float*)d_in[9];
    const float* b_c2 = (const float*)d_in[10];
    const float* W_lp = (const float*)d_in[11];
    const float* b_lp = (const float*)d_in[12];
    float* out = (float*)d_out;

    float *p_h1, *p_h2, *p_xg, *p_dis, *p_Wp;
    __half *p_xwh, *p_t40h;
    cudaGetSymbolAddress((void**)&p_h1,   g_h1);
    cudaGetSymbolAddress((void**)&p_h2,   g_h2);
    cudaGetSymbolAddress((void**)&p_xg,   g_xg);
    cudaGetSymbolAddress((void**)&p_dis,  g_dis);
    cudaGetSymbolAddress((void**)&p_Wp,   g_Wp);
    cudaGetSymbolAddress((void**)&p_xwh,  g_xwh);
    cudaGetSymbolAddress((void**)&p_t40h, g_t40h);

    const int B = 256;
    const int GR  = (NN + 63) / 64;
    const int GRM = (NN + 127) / 128;

    const int SH128 = 2 * 64 * padw(128 / 2) * 4;   // 34816
    const int SH64  = 2 * 64 * padw(64 / 2) * 4;    // 18432
    const int SH192 = 2 * 64 * padw(192 / 2) * 4;   // 51200
    cudaFuncSetAttribute(k_mma_h<D, 0>,   cudaFuncAttributeMaxDynamicSharedMemorySize, SH64);
    cudaFuncSetAttribute(k_mma_h<FIN, D>, cudaFuncAttributeMaxDynamicSharedMemorySize, SH192);
    cudaFuncSetAttribute(k_fill_gemm,     cudaFuncAttributeMaxDynamicSharedMemorySize, SH128);

    // ---- CSR build (GEMM1 fused into fill) ----
    k_cnt<<<(EE + B - 1) / B, B>>>(eidx, hidx);
    k_scan1f<<<dim3((NN + 1023) / 1024, 4), 256>>>(W_c2, b_c2, W_lp, b_lp);
    k_scan3f<<<dim3((NN + 255) / 256, 3), 256>>>();
    k_fill_gemm<<<GEMM_BLKS + (EE + B - 1) / B, B, SH128>>>(eidx, hidx, x, W_h1, p_xwh);

    // ---- hyperconv 1 (fp16 gathers) ----
    k_gath_he<<<(HEN * 8 + B - 1) / B, B>>>();
    k_gath_e2n<<<(NN * 8 + B - 1) / B, B>>>(b_h1, p_h1, 1);

    // ---- hyperconv 2 ----
    k_mma_h<D, 0><<<GRM, 128, SH64>>>(p_h1, nullptr, W_h2, p_xwh, nullptr);
    k_gath_he<<<(HEN * 8 + B - 1) / B, B>>>();
    k_gath_e2n<<<(NN * 8 + B - 1) / B, B>>>(b_h2, p_h2, 0);

    // ---- gcn 1 (concat input, dis-prescaled, fp16 xwd) ----
    k_mma_h<FIN, D><<<GRM, 128, SH192>>>(x, p_h2, W_c1, p_xwh, p_dis);
    k_gcn64h<<<(NN * 8 + B - 1) / B, B>>>(b_c1, p_xg);

    // ---- gcn 2 with folded head (fp16 t40) ----
    k_gemm_h<D, NC><<<GR, 160>>>(p_xg, p_Wp, p_t40h, p_dis);
    k_gcn40h<<<(NN * 5 + 319) / 320, 320>>>(out);
}